// round 5
// baseline (speedup 1.0000x reference)
#include <cuda_runtime.h>
#include <math.h>

// Problem constants
#define B_   2
#define C_   4
#define F_   512
#define H_   8
#define W_   1024
#define DH_  64
#define KW   3
#define BC_  (B_*C_)          // 8
#define BCH_ (B_*C_*H_)       // 64
#define PLANE_ (F_*W_)        // 524288 per (b,c)
#define TOT_   (B_*C_*F_*W_)  // 4194304

// Scratch (device globals; no allocations allowed)
__device__ float g_lin[3][TOT_];
__device__ float g_conv[3][TOT_];
__device__ float g_abuf[TOT_];
__device__ float2 g_rottab[32 * 1024];   // [j][w] -> (cos, sin)

// ---------------------------------------------------------------------------
// Rotary cos/sin table: j in [0,32), w in [0,1024)
// ---------------------------------------------------------------------------
__global__ void __launch_bounds__(256) rot_table_kernel()
{
    int id = blockIdx.x * 256 + threadIdx.x;
    if (id >= 32 * 1024) return;
    int j = id >> 10, w = id & (W_ - 1);
    float inv = (float)exp(-log(10000.0) * ((double)(2 * j) / 64.0));
    float ang = (float)w * inv;
    float sn, cs;
    sincosf(ang, &sn, &cs);
    g_rottab[id] = make_float2(cs, sn);
}

// ---------------------------------------------------------------------------
// Per-channel GEMM: Y[bc][g][w] = sum_f Wt[c][g][f] * X[bc][f][w]
// 128x128 tile, K-tile 8, 256 threads, 8x8 microtile, double-buffered smem.
// ---------------------------------------------------------------------------
__global__ void __launch_bounds__(256) gemm128_kernel(
    const float* __restrict__ Wt, const float* __restrict__ X, float* __restrict__ Y)
{
    const int bc = blockIdx.z;
    const int c  = bc % C_;
    const float* Wc = Wt + (size_t)c * F_ * F_;
    const float* Xb = X  + (size_t)bc * PLANE_;
    float*       Yb = Y  + (size_t)bc * PLANE_;

    __shared__ float As[2][8][128];   // [buf][k][m]
    __shared__ float Bs[2][8][128];   // [buf][k][n]

    const int tid = threadIdx.x;
    const int tx  = tid & 15;
    const int ty  = tid >> 4;
    const int m0  = blockIdx.y * 128;
    const int n0  = blockIdx.x * 128;

    // Global-load mapping
    const int ar = tid >> 1;          // A row 0..127
    const int ak = (tid & 1) * 4;     // A k sub-offset 0/4
    const int bkr = tid >> 5;         // B k row 0..7
    const int bnc = (tid & 31) * 4;   // B col 0..124

    const float* Ag = Wc + (size_t)(m0 + ar) * F_ + ak;
    const float* Bg = Xb + (size_t)bkr * W_ + n0 + bnc;

    float acc[8][8] = {};

    // prologue: tile 0
    {
        float4 a = *(const float4*)(Ag);
        float4 b = *(const float4*)(Bg);
        As[0][ak+0][ar] = a.x; As[0][ak+1][ar] = a.y;
        As[0][ak+2][ar] = a.z; As[0][ak+3][ar] = a.w;
        *(float4*)&Bs[0][bkr][bnc] = b;
    }
    __syncthreads();

    int buf = 0;
    for (int k0 = 0; k0 < F_; k0 += 8) {
        float4 an, bn4;
        const bool pf = (k0 + 8) < F_;
        if (pf) {
            an  = *(const float4*)(Ag + k0 + 8);
            bn4 = *(const float4*)(Bg + (size_t)(k0 + 8) * W_);
        }
        #pragma unroll
        for (int kk = 0; kk < 8; kk++) {
            float4 a0 = *(const float4*)&As[buf][kk][ty*4];
            float4 a1 = *(const float4*)&As[buf][kk][64 + ty*4];
            float4 b0 = *(const float4*)&Bs[buf][kk][tx*4];
            float4 b1 = *(const float4*)&Bs[buf][kk][64 + tx*4];
            float ra[8] = {a0.x,a0.y,a0.z,a0.w,a1.x,a1.y,a1.z,a1.w};
            float rb[8] = {b0.x,b0.y,b0.z,b0.w,b1.x,b1.y,b1.z,b1.w};
            #pragma unroll
            for (int i = 0; i < 8; i++)
                #pragma unroll
                for (int j = 0; j < 8; j++)
                    acc[i][j] += ra[i] * rb[j];
        }
        if (pf) {
            As[buf^1][ak+0][ar] = an.x; As[buf^1][ak+1][ar] = an.y;
            As[buf^1][ak+2][ar] = an.z; As[buf^1][ak+3][ar] = an.w;
            *(float4*)&Bs[buf^1][bkr][bnc] = bn4;
        }
        __syncthreads();
        buf ^= 1;
    }

    #pragma unroll
    for (int i = 0; i < 8; i++) {
        int m = m0 + ((i < 4) ? (ty*4 + i) : (64 + ty*4 + i - 4));
        float* yr = Yb + (size_t)m * W_ + n0;
        *(float4*)(yr + tx*4)      = make_float4(acc[i][0],acc[i][1],acc[i][2],acc[i][3]);
        *(float4*)(yr + 64 + tx*4) = make_float4(acc[i][4],acc[i][5],acc[i][6],acc[i][7]);
    }
}

// ---------------------------------------------------------------------------
// Fused Conv2d(C,C,(1,3),pad=(0,1)) + bias + optional rotary.
// Each thread computes the feature pair (2p, 2p+1) at one (b,o,w).
// ---------------------------------------------------------------------------
template<int ROT>
__global__ void __launch_bounds__(256) conv_rot_kernel(
    const float* __restrict__ X, const float* __restrict__ Wc,
    const float* __restrict__ bias, float* __restrict__ Y)
{
    __shared__ float ws[C_*C_*KW];
    __shared__ float bs[C_];
    if (threadIdx.x < C_*C_*KW) ws[threadIdx.x] = Wc[threadIdx.x];
    if (threadIdx.x < C_)       bs[threadIdx.x] = bias[threadIdx.x];
    __syncthreads();

    int idx = blockIdx.x * 256 + threadIdx.x;     // over TOT_/2
    if (idx >= TOT_/2) return;
    int w  = idx & (W_ - 1);
    int fp = (idx >> 10) & 255;                   // feature pair 0..255
    int o  = (idx >> 18) & (C_ - 1);
    int b  = idx >> 20;
    int f0 = fp * 2;

    float s0 = bs[o], s1 = bs[o];
    #pragma unroll
    for (int i = 0; i < C_; i++) {
        const float* x0 = X + ((size_t)(b*C_ + i) * F_ + f0) * W_ + w;
        const float* x1 = x0 + W_;
        const float* wr = ws + (o*C_ + i) * KW;
        if (w > 0)       { s0 += wr[0] * x0[-1]; s1 += wr[0] * x1[-1]; }
                           s0 += wr[1] * x0[0];  s1 += wr[1] * x1[0];
        if (w < W_ - 1)  { s0 += wr[2] * x0[1];  s1 += wr[2] * x1[1]; }
    }

    size_t obase = ((size_t)(b*C_ + o) * F_ + f0) * W_ + w;
    if (ROT) {
        int j = fp & 31;                          // pair index within head
        float2 cssn = g_rottab[j * W_ + w];
        float r0 = s0 * cssn.x - s1 * cssn.y;
        float r1 = s1 * cssn.x + s0 * cssn.y;
        Y[obase]      = r0;
        Y[obase + W_] = r1;
    } else {
        Y[obase]      = s0;
        Y[obase + W_] = s1;
    }
}

// ---------------------------------------------------------------------------
// qk[bch][q][k] = (1/sqrt(512)) * sum_d Q[d][q]*K[d][k] + prev + mask
// 128x128 tile per block, 8x8 microtile, K=64 fully in (dynamic) smem.
// ---------------------------------------------------------------------------
#define QK_SMEM (2 * 64 * 128 * 4)

__global__ void __launch_bounds__(256) qk128_kernel(
    const float* __restrict__ Q, const float* __restrict__ Kb,
    const float* __restrict__ prev, const float* __restrict__ mask,
    float* __restrict__ qk)
{
    extern __shared__ float sm[];
    float (*Qs)[128] = (float (*)[128])sm;
    float (*Ks)[128] = (float (*)[128])(sm + 64 * 128);

    const int bch = blockIdx.z;
    const int h   = bch & (H_ - 1);
    const int bc  = bch >> 3;
    const size_t fbase = (size_t)bc * F_ + h * DH_;
    const int q0 = blockIdx.y * 128;
    const int k0 = blockIdx.x * 128;

    const int tid = threadIdx.x;
    #pragma unroll
    for (int t = 0; t < 8; t++) {
        int i  = tid + t * 256;
        int d  = i >> 5;
        int c4 = (i & 31) * 4;
        *(float4*)&Qs[d][c4] = *(const float4*)(Q  + (fbase + d) * W_ + q0 + c4);
        *(float4*)&Ks[d][c4] = *(const float4*)(Kb + (fbase + d) * W_ + k0 + c4);
    }
    __syncthreads();

    const int tx = tid & 15, ty = tid >> 4;
    float acc[8][8] = {};
    #pragma unroll 8
    for (int d = 0; d < 64; d++) {
        float4 a0 = *(const float4*)&Qs[d][ty*4];
        float4 a1 = *(const float4*)&Qs[d][64 + ty*4];
        float4 b0 = *(const float4*)&Ks[d][tx*4];
        float4 b1 = *(const float4*)&Ks[d][64 + tx*4];
        float ra[8] = {a0.x,a0.y,a0.z,a0.w,a1.x,a1.y,a1.z,a1.w};
        float rb[8] = {b0.x,b0.y,b0.z,b0.w,b1.x,b1.y,b1.z,b1.w};
        #pragma unroll
        for (int i = 0; i < 8; i++)
            #pragma unroll
            for (int j = 0; j < 8; j++)
                acc[i][j] += ra[i] * rb[j];
    }

    const float scale = 0.044194173824159216f;   // 1/sqrt(512)
    #pragma unroll
    for (int i = 0; i < 8; i++) {
        int q = q0 + ((i < 4) ? (ty*4 + i) : (64 + ty*4 + i - 4));
        size_t orow = ((size_t)bch * W_ + q) * W_ + k0;
        const float* mrow = mask + (size_t)q * W_ + k0;
        #pragma unroll
        for (int hhalf = 0; hhalf < 2; hhalf++) {
            int col = hhalf * 64 + tx * 4;
            float4 pv = *(const float4*)(prev + orow + col);
            float4 mv = *(const float4*)(mrow + col);
            float4 r;
            r.x = acc[i][hhalf*4+0]*scale + pv.x + mv.x;
            r.y = acc[i][hhalf*4+1]*scale + pv.y + mv.y;
            r.z = acc[i][hhalf*4+2]*scale + pv.z + mv.z;
            r.w = acc[i][hhalf*4+3]*scale + pv.w + mv.w;
            *(float4*)(qk + orow + col) = r;
        }
    }
}

// ---------------------------------------------------------------------------
// Fused softmax + P*V.  One block = (bch, 32 q rows).
// Phase 1: softmax rows into smem p[32][1024] (exp'd), rs = 1/rowsum.
// Phase 2: each thread owns 2 d rows (streamed via float4 LDG from L1/L2)
//          x 4 q rows (float4 broadcast LDS from p). No V smem, no syncs.
// ---------------------------------------------------------------------------
#define SMAX_SMEM ((32*1024 + 32) * 4)

__global__ void __launch_bounds__(256) softmax_av_kernel(
    const float* __restrict__ qk, const float* __restrict__ V, float* __restrict__ A)
{
    extern __shared__ float sm[];
    float* p  = sm;                   // 32 * 1024 (exp'd rows)
    float* rs = sm + 32*1024;         // 32 (1/rowsum)

    const int bch = blockIdx.y;
    const int q0  = blockIdx.x * 32;
    const int tid = threadIdx.x, lane = tid & 31, warp = tid >> 5;

    // ---- Phase 1: softmax of 32 rows (each warp owns 4 rows), float4 I/O
    for (int r = warp*4; r < warp*4 + 4; r++) {
        const float* row = qk + ((size_t)bch * W_ + q0 + r) * W_;
        float* pr = p + r * W_;
        float mx = -1e30f;
        #pragma unroll
        for (int i = 0; i < 8; i++) {
            float4 v = *(const float4*)(row + lane*4 + i*128);
            *(float4*)(pr + lane*4 + i*128) = v;
            mx = fmaxf(mx, fmaxf(fmaxf(v.x, v.y), fmaxf(v.z, v.w)));
        }
        #pragma unroll
        for (int o = 16; o; o >>= 1) mx = fmaxf(mx, __shfl_xor_sync(0xffffffffu, mx, o));
        float s = 0.f;
        #pragma unroll
        for (int i = 0; i < 8; i++) {
            float4 v = *(const float4*)(pr + lane*4 + i*128);
            v.x = __expf(v.x - mx); v.y = __expf(v.y - mx);
            v.z = __expf(v.z - mx); v.w = __expf(v.w - mx);
            *(float4*)(pr + lane*4 + i*128) = v;
            s += v.x + v.y + v.z + v.w;
        }
        #pragma unroll
        for (int o = 16; o; o >>= 1) s += __shfl_xor_sync(0xffffffffu, s, o);
        if (lane == 0) rs[r] = 1.0f / s;
    }
    __syncthreads();

    // ---- Phase 2: a[d][q] = sum_k p[q][k] * V[d][k]
    const int h  = bch & (H_ - 1);
    const int bc = bch >> 3;
    const size_t fbase = (size_t)bc * F_ + h * DH_;
    const int d0 = (tid & 31) * 2;     // 2 d rows per thread
    const int qr = (tid >> 5) * 4;     // 4 q rows per warp

    const float* va = V + (fbase + d0) * W_;
    const float* vb = va + W_;
    const float* pp0 = p + (qr+0) * W_;
    const float* pp1 = p + (qr+1) * W_;
    const float* pp2 = p + (qr+2) * W_;
    const float* pp3 = p + (qr+3) * W_;

    float acc[2][4] = {};
    #pragma unroll 4
    for (int kk = 0; kk < W_; kk += 4) {
        float4 v0 = *(const float4*)(va + kk);
        float4 v1 = *(const float4*)(vb + kk);
        float4 x0 = *(const float4*)(pp0 + kk);
        float4 x1 = *(const float4*)(pp1 + kk);
        float4 x2 = *(const float4*)(pp2 + kk);
        float4 x3 = *(const float4*)(pp3 + kk);
        float pv0[4] = {v0.x, v0.y, v0.z, v0.w};
        float pv1[4] = {v1.x, v1.y, v1.z, v1.w};
        float px[4][4] = {{x0.x,x0.y,x0.z,x0.w},{x1.x,x1.y,x1.z,x1.w},
                          {x2.x,x2.y,x2.z,x2.w},{x3.x,x3.y,x3.z,x3.w}};
        #pragma unroll
        for (int t = 0; t < 4; t++) {
            #pragma unroll
            for (int j = 0; j < 4; j++) {
                acc[0][j] += pv0[t] * px[j][t];
                acc[1][j] += pv1[t] * px[j][t];
            }
        }
    }

    #pragma unroll
    for (int i = 0; i < 2; i++) {
        float4 r = make_float4(acc[i][0]*rs[qr+0], acc[i][1]*rs[qr+1],
                               acc[i][2]*rs[qr+2], acc[i][3]*rs[qr+3]);
        *(float4*)(A + (fbase + d0 + i) * W_ + q0 + qr) = r;
    }
}

// ---------------------------------------------------------------------------
extern "C" void kernel_launch(void* const* d_in, const int* in_sizes, int n_in,
                              void* d_out, int out_size)
{
    const float* x    = (const float*)d_in[0];
    const float* prev = (const float*)d_in[1];
    const float* mask = (const float*)d_in[2];
    const float* wq   = (const float*)d_in[3];
    const float* wqc  = (const float*)d_in[4];
    const float* bq   = (const float*)d_in[5];
    const float* wk   = (const float*)d_in[6];
    const float* wkc  = (const float*)d_in[7];
    const float* bk   = (const float*)d_in[8];
    const float* wv   = (const float*)d_in[9];
    const float* wvc  = (const float*)d_in[10];
    const float* bv   = (const float*)d_in[11];
    const float* wo   = (const float*)d_in[12];

    float* out = (float*)d_out;            // [B,C,F,W]
    float* qk  = out + (size_t)TOT_;       // [B,C,H,W,W]

    float *lin_base, *conv_base, *abuf;
    cudaGetSymbolAddress((void**)&lin_base,  g_lin);
    cudaGetSymbolAddress((void**)&conv_base, g_conv);
    cudaGetSymbolAddress((void**)&abuf,      g_abuf);
    float* lin0  = lin_base;
    float* lin1  = lin_base + (size_t)TOT_;
    float* lin2  = lin_base + (size_t)2*TOT_;
    float* cbuf0 = conv_base;
    float* cbuf1 = conv_base + (size_t)TOT_;
    float* cbuf2 = conv_base + (size_t)2*TOT_;

    rot_table_kernel<<<128, 256>>>();

    dim3 gg(W_/128, F_/128, BC_);  // 8, 4, 8
    gemm128_kernel<<<gg, 256>>>(wq, x, lin0);
    gemm128_kernel<<<gg, 256>>>(wk, x, lin1);
    gemm128_kernel<<<gg, 256>>>(wv, x, lin2);

    int cblocks = (TOT_/2) / 256;
    conv_rot_kernel<1><<<cblocks, 256>>>(lin0, wqc, bq, cbuf0);
    conv_rot_kernel<1><<<cblocks, 256>>>(lin1, wkc, bk, cbuf1);
    conv_rot_kernel<0><<<cblocks, 256>>>(lin2, wvc, bv, cbuf2);

    cudaFuncSetAttribute(qk128_kernel,
                         cudaFuncAttributeMaxDynamicSharedMemorySize, QK_SMEM);
    qk128_kernel<<<dim3(W_/128, W_/128, BCH_), 256, QK_SMEM>>>(cbuf0, cbuf1, prev, mask, qk);

    cudaFuncSetAttribute(softmax_av_kernel,
                         cudaFuncAttributeMaxDynamicSharedMemorySize, SMAX_SMEM);
    softmax_av_kernel<<<dim3(W_/32, BCH_), 256, SMAX_SMEM>>>(qk, cbuf2, abuf);

    gemm128_kernel<<<gg, 256>>>(wo, abuf, out);
}

// round 7
// speedup vs baseline: 2.9283x; 2.9283x over previous
#include <cuda_runtime.h>
#include <math.h>

// Problem constants
#define B_   2
#define C_   4
#define F_   512
#define H_   8
#define W_   1024
#define DH_  64
#define KW   3
#define BC_  (B_*C_)          // 8
#define BCH_ (B_*C_*H_)       // 64
#define PLANE_ (F_*W_)        // 524288
#define TOT_   (B_*C_*F_*W_)  // 4194304
#define NROWS_ (BCH_*W_)      // 65536 qk rows

// ---------------------------------------------------------------------------
// Scratch (device globals; no allocations allowed)
// ---------------------------------------------------------------------------
__device__ float g_lin[3][TOT_];     // q,k,v linear outputs [bc][f][w]
__device__ float g_conv[3][TOT_];    // post conv(+rotary) [bc][f][w]
__device__ float g_xt[TOT_];         // x transposed [bc][w][f]
__device__ float g_qt[TOT_];         // Q transposed [bch][w][d]
__device__ float g_kt[TOT_];         // K transposed [bch][w][d]
__device__ float g_atT[TOT_];        // attention out [bc][w][f]
__device__ float g_mx[NROWS_];       // row max of qk
__device__ float g_rs[NROWS_];       // 1/rowsum of exp
__device__ float2 g_rottab[32 * 1024];

// ---------------------------------------------------------------------------
// tf32 helpers (legacy mma.sync path — works on plain sm_103 target)
// ---------------------------------------------------------------------------
__device__ __forceinline__ unsigned tf32r(float x) {
    unsigned u;
    asm("cvt.rna.tf32.f32 %0, %1;" : "=r"(u) : "f"(x));
    return u;
}
#define MMA8(d, a, b) \
    asm volatile("mma.sync.aligned.m16n8k8.row.col.f32.tf32.tf32.f32 " \
        "{%0,%1,%2,%3}, {%4,%5,%6,%7}, {%8,%9}, {%0,%1,%2,%3};" \
        : "+f"((d)[0]), "+f"((d)[1]), "+f"((d)[2]), "+f"((d)[3]) \
        : "r"((a)[0]), "r"((a)[1]), "r"((a)[2]), "r"((a)[3]), \
          "r"((b)[0]), "r"((b)[1]))

// ---------------------------------------------------------------------------
// Rotary cos/sin table
// ---------------------------------------------------------------------------
__global__ void __launch_bounds__(256) rot_table_kernel()
{
    int id = blockIdx.x * 256 + threadIdx.x;
    if (id >= 32 * 1024) return;
    int j = id >> 10, w = id & (W_ - 1);
    float inv = (float)exp(-log(10000.0) * ((double)(2 * j) / 64.0));
    float ang = (float)w * inv;
    float sn, cs;
    sincosf(ang, &sn, &cs);
    g_rottab[id] = make_float2(cs, sn);
}

// ---------------------------------------------------------------------------
// Plane transpose: in [plane][R][W_] -> out [plane][W_][R]
// ---------------------------------------------------------------------------
__global__ void transpose_kernel(const float* __restrict__ in,
                                 float* __restrict__ out, int R)
{
    __shared__ float t[32][33];
    const int p  = blockIdx.z;
    const int r0 = blockIdx.y * 32, w0 = blockIdx.x * 32;
    const int tx = threadIdx.x, ty = threadIdx.y;        // (32, 8)
    const float* ip = in  + (size_t)p * R * W_;
    float*       op = out + (size_t)p * R * W_;
    #pragma unroll
    for (int i = 0; i < 4; i++)
        t[ty + i*8][tx] = ip[(size_t)(r0 + ty + i*8) * W_ + w0 + tx];
    __syncthreads();
    #pragma unroll
    for (int i = 0; i < 4; i++)
        op[(size_t)(w0 + ty + i*8) * R + r0 + tx] = t[tx][ty + i*8];
}

// ---------------------------------------------------------------------------
// tf32 GEMM: Y[bc][m][n] = sum_k A[c][m][k] * B[bc][n][k]
// M=512, N=1024, K=512.  CTA 128x128, BK=32, 8 warps (2x4), warp tile 64x32.
// ---------------------------------------------------------------------------
__global__ void __launch_bounds__(256, 2) gemm_tf32_kernel(
    const float* __restrict__ Wt,   // [C][512][512]
    const float* __restrict__ Bm,   // [BC][1024][512]
    float* __restrict__ Y)          // [BC][512][1024]
{
    __shared__ unsigned As[128][36];
    __shared__ unsigned Bs[128][36];

    const int tid = threadIdx.x;
    const int wid = tid >> 5, lane = tid & 31;
    const int g = lane >> 2, t4 = lane & 3;
    const int bc = blockIdx.z, c = bc & (C_ - 1);
    const int m0 = blockIdx.y * 128, n0 = blockIdx.x * 128;
    const int wm0 = (wid >> 2) * 64, wn0 = (wid & 3) * 32;

    const float* Ab = Wt + ((size_t)c  * F_ + m0) * F_;
    const float* Bb = Bm + ((size_t)bc * W_ + n0) * F_;

    const int lr = tid >> 1;           // 0..127
    const int lc = (tid & 1) * 16;     // 0/16

    float acc[4][4][4] = {};

    for (int kt = 0; kt < 16; kt++) {
        const float* ap = Ab + (size_t)lr * F_ + kt*32 + lc;
        const float* bp = Bb + (size_t)lr * F_ + kt*32 + lc;
        float4 va[4], vb[4];
        #pragma unroll
        for (int j = 0; j < 4; j++) { va[j] = *(const float4*)(ap + 4*j); }
        #pragma unroll
        for (int j = 0; j < 4; j++) { vb[j] = *(const float4*)(bp + 4*j); }
        __syncthreads();
        #pragma unroll
        for (int j = 0; j < 4; j++) {
            uint4 ua = make_uint4(tf32r(va[j].x), tf32r(va[j].y), tf32r(va[j].z), tf32r(va[j].w));
            uint4 ub = make_uint4(tf32r(vb[j].x), tf32r(vb[j].y), tf32r(vb[j].z), tf32r(vb[j].w));
            *(uint4*)&As[lr][lc + 4*j] = ua;
            *(uint4*)&Bs[lr][lc + 4*j] = ub;
        }
        __syncthreads();
        #pragma unroll
        for (int k8 = 0; k8 < 4; k8++) {
            const int kk = k8 * 8;
            unsigned a[4][4], b[4][2];
            #pragma unroll
            for (int mf = 0; mf < 4; mf++) {
                int r = wm0 + mf*16 + g;
                a[mf][0] = As[r][kk + t4];
                a[mf][1] = As[r + 8][kk + t4];
                a[mf][2] = As[r][kk + t4 + 4];
                a[mf][3] = As[r + 8][kk + t4 + 4];
            }
            #pragma unroll
            for (int nf = 0; nf < 4; nf++) {
                int r = wn0 + nf*8 + g;
                b[nf][0] = Bs[r][kk + t4];
                b[nf][1] = Bs[r][kk + t4 + 4];
            }
            #pragma unroll
            for (int mf = 0; mf < 4; mf++)
                #pragma unroll
                for (int nf = 0; nf < 4; nf++)
                    MMA8(acc[mf][nf], a[mf], b[nf]);
        }
    }

    // epilogue
    #pragma unroll
    for (int mf = 0; mf < 4; mf++) {
        #pragma unroll
        for (int nf = 0; nf < 4; nf++) {
            int m = m0 + wm0 + mf*16 + g;
            int n = n0 + wn0 + nf*8 + 2*t4;
            float* y0 = Y + ((size_t)bc * F_ + m) * W_ + n;
            *(float2*)y0            = make_float2(acc[mf][nf][0], acc[mf][nf][1]);
            *(float2*)(y0 + 8*W_)   = make_float2(acc[mf][nf][2], acc[mf][nf][3]);
        }
    }
}

// ---------------------------------------------------------------------------
// Fused Conv2d(C,C,(1,3),pad=(0,1)) + bias + optional rotary.
// ---------------------------------------------------------------------------
template<int ROT>
__global__ void __launch_bounds__(256) conv_rot_kernel(
    const float* __restrict__ X, const float* __restrict__ Wc,
    const float* __restrict__ bias, float* __restrict__ Y)
{
    __shared__ float ws[C_*C_*KW];
    __shared__ float bs[C_];
    if (threadIdx.x < C_*C_*KW) ws[threadIdx.x] = Wc[threadIdx.x];
    if (threadIdx.x < C_)       bs[threadIdx.x] = bias[threadIdx.x];
    __syncthreads();

    int idx = blockIdx.x * 256 + threadIdx.x;     // over TOT_/2
    if (idx >= TOT_/2) return;
    int w  = idx & (W_ - 1);
    int fp = (idx >> 10) & 255;
    int o  = (idx >> 18) & (C_ - 1);
    int b  = idx >> 20;
    int f0 = fp * 2;

    float s0 = bs[o], s1 = bs[o];
    #pragma unroll
    for (int i = 0; i < C_; i++) {
        const float* x0 = X + ((size_t)(b*C_ + i) * F_ + f0) * W_ + w;
        const float* x1 = x0 + W_;
        const float* wr = ws + (o*C_ + i) * KW;
        if (w > 0)       { s0 += wr[0] * x0[-1]; s1 += wr[0] * x1[-1]; }
                           s0 += wr[1] * x0[0];  s1 += wr[1] * x1[0];
        if (w < W_ - 1)  { s0 += wr[2] * x0[1];  s1 += wr[2] * x1[1]; }
    }

    size_t obase = ((size_t)(b*C_ + o) * F_ + f0) * W_ + w;
    if (ROT) {
        int j = fp & 31;
        float2 cssn = g_rottab[j * W_ + w];
        Y[obase]      = s0 * cssn.x - s1 * cssn.y;
        Y[obase + W_] = s1 * cssn.x + s0 * cssn.y;
    } else {
        Y[obase]      = s0;
        Y[obase + W_] = s1;
    }
}

// ---------------------------------------------------------------------------
// qk = scale*Qt.Kt^T + prev + mask   via tf32 mma.
// Per (bch): M=N=1024, K=64.  CTA 128x128, one-shot smem, 8 warps (2x4).
// ---------------------------------------------------------------------------
#define QK_SMEM (2 * 128 * 68 * 4)

__global__ void __launch_bounds__(256, 2) qk_mma_kernel(
    const float* __restrict__ Qt, const float* __restrict__ Kt,
    const float* __restrict__ prev, const float* __restrict__ mask,
    float* __restrict__ qk)
{
    extern __shared__ unsigned qsm[];
    unsigned (*Qs)[68] = (unsigned (*)[68])qsm;
    unsigned (*Ks)[68] = (unsigned (*)[68])(qsm + 128 * 68);

    const int tid = threadIdx.x;
    const int wid = tid >> 5, lane = tid & 31;
    const int g = lane >> 2, t4 = lane & 3;
    const int bch = blockIdx.z;
    const int q0 = blockIdx.y * 128, k0 = blockIdx.x * 128;
    const int wm0 = (wid >> 2) * 64, wn0 = (wid & 3) * 32;

    const float* Qb = Qt + ((size_t)bch * W_ + q0) * DH_;
    const float* Kb = Kt + ((size_t)bch * W_ + k0) * DH_;

    #pragma unroll
    for (int t = 0; t < 8; t++) {
        int idx = tid + t * 256;          // 0..2047
        int row = idx >> 4;
        int c4  = (idx & 15) * 4;
        float4 vq = *(const float4*)(Qb + (size_t)row * DH_ + c4);
        float4 vk = *(const float4*)(Kb + (size_t)row * DH_ + c4);
        *(uint4*)&Qs[row][c4] = make_uint4(tf32r(vq.x), tf32r(vq.y), tf32r(vq.z), tf32r(vq.w));
        *(uint4*)&Ks[row][c4] = make_uint4(tf32r(vk.x), tf32r(vk.y), tf32r(vk.z), tf32r(vk.w));
    }
    __syncthreads();

    float acc[4][4][4] = {};
    #pragma unroll
    for (int k8 = 0; k8 < 8; k8++) {
        const int kk = k8 * 8;
        unsigned a[4][4], b[4][2];
        #pragma unroll
        for (int mf = 0; mf < 4; mf++) {
            int r = wm0 + mf*16 + g;
            a[mf][0] = Qs[r][kk + t4];
            a[mf][1] = Qs[r + 8][kk + t4];
            a[mf][2] = Qs[r][kk + t4 + 4];
            a[mf][3] = Qs[r + 8][kk + t4 + 4];
        }
        #pragma unroll
        for (int nf = 0; nf < 4; nf++) {
            int r = wn0 + nf*8 + g;
            b[nf][0] = Ks[r][kk + t4];
            b[nf][1] = Ks[r][kk + t4 + 4];
        }
        #pragma unroll
        for (int mf = 0; mf < 4; mf++)
            #pragma unroll
            for (int nf = 0; nf < 4; nf++)
                MMA8(acc[mf][nf], a[mf], b[nf]);
    }

    const float scale = 0.044194173824159216f;   // 1/sqrt(512)
    #pragma unroll
    for (int mf = 0; mf < 4; mf++) {
        #pragma unroll
        for (int nf = 0; nf < 4; nf++) {
            int q  = q0 + wm0 + mf*16 + g;
            int kp = k0 + wn0 + nf*8 + 2*t4;
            #pragma unroll
            for (int rr = 0; rr < 2; rr++) {
                int qq = q + rr * 8;
                size_t o = ((size_t)bch * W_ + qq) * W_ + kp;
                float2 pv = *(const float2*)(prev + o);
                float2 mv = *(const float2*)(mask + (size_t)qq * W_ + kp);
                float2 r;
                r.x = acc[mf][nf][2*rr+0] * scale + pv.x + mv.x;
                r.y = acc[mf][nf][2*rr+1] * scale + pv.y + mv.y;
                *(float2*)(qk + o) = r;
            }
        }
    }
}

// ---------------------------------------------------------------------------
// Row stats: mx[row] = max(qk[row]), rs[row] = 1/sum(exp(qk[row]-mx)).
// One warp per row.
// ---------------------------------------------------------------------------
__global__ void __launch_bounds__(256) rowstats_kernel(
    const float* __restrict__ qk, float* __restrict__ mx, float* __restrict__ rs)
{
    const int row  = blockIdx.x * 8 + (threadIdx.x >> 5);
    const int lane = threadIdx.x & 31;
    const float* r = qk + (size_t)row * W_;

    float v[32];
    float m = -1e30f;
    #pragma unroll
    for (int i = 0; i < 8; i++) {
        float4 x = *(const float4*)(r + lane*4 + i*128);
        v[4*i] = x.x; v[4*i+1] = x.y; v[4*i+2] = x.z; v[4*i+3] = x.w;
        m = fmaxf(m, fmaxf(fmaxf(x.x, x.y), fmaxf(x.z, x.w)));
    }
    #pragma unroll
    for (int o = 16; o; o >>= 1) m = fmaxf(m, __shfl_xor_sync(0xffffffffu, m, o));
    float s = 0.f;
    #pragma unroll
    for (int i = 0; i < 32; i++) s += __expf(v[i] - m);
    #pragma unroll
    for (int o = 16; o; o >>= 1) s += __shfl_xor_sync(0xffffffffu, s, o);
    if (lane == 0) { mx[row] = m; rs[row] = 1.0f / s; }
}

// ---------------------------------------------------------------------------
// AV: AT[bc][q][h*64+d] = (1/s_q) * sum_k exp(qk[bch][q][k]-mx_q) * V[bc][h*64+d][k]
// CTA: 128 q x 64 d per bch.  BK=64, 16 K-iters.  8 warps (4x2), warp 32x32.
// ---------------------------------------------------------------------------
#define AV_SMEM ((128*68 + 64*68 + 256) * 4)

__global__ void __launch_bounds__(256, 2) av_mma_kernel(
    const float* __restrict__ qk, const float* __restrict__ V,
    const float* __restrict__ mxv, const float* __restrict__ rsv,
    float* __restrict__ AT)
{
    extern __shared__ unsigned asm_[];
    unsigned (*Ps)[68] = (unsigned (*)[68])asm_;
    unsigned (*Vs)[68] = (unsigned (*)[68])(asm_ + 128 * 68);
    float* smx = (float*)(asm_ + 128*68 + 64*68);
    float* srs = smx + 128;

    const int tid = threadIdx.x;
    const int wid = tid >> 5, lane = tid & 31;
    const int g = lane >> 2, t4 = lane & 3;
    const int bch = blockIdx.y;
    const int q0  = blockIdx.x * 128;
    const int h   = bch & (H_ - 1);
    const int bc  = bch >> 3;
    const int wm0 = (wid >> 1) * 32, wn0 = (wid & 1) * 32;

    if (tid < 128) {
        smx[tid] = mxv[(size_t)bch * W_ + q0 + tid];
        srs[tid] = rsv[(size_t)bch * W_ + q0 + tid];
    }

    const float* qrow = qk + ((size_t)bch * W_ + q0) * W_;
    const float* Vb   = V + ((size_t)bc * F_ + h * DH_) * W_;

    float acc[2][4][4] = {};
    for (int kt = 0; kt < 16; kt++) {
        const int k0 = kt * 64;
        __syncthreads();
        #pragma unroll
        for (int t = 0; t < 8; t++) {
            int idx = tid + t * 256;          // 0..2047
            int row = idx >> 4;
            int c4  = (idx & 15) * 4;
            float4 x = *(const float4*)(qrow + (size_t)row * W_ + k0 + c4);
            float m = smx[row];
            *(uint4*)&Ps[row][c4] = make_uint4(
                tf32r(__expf(x.x - m)), tf32r(__expf(x.y - m)),
                tf32r(__expf(x.z - m)), tf32r(__expf(x.w - m)));
        }
        #pragma unroll
        for (int t = 0; t < 4; t++) {
            int idx = tid + t * 256;          // 0..1023
            int row = idx >> 4;
            int c4  = (idx & 15) * 4;
            float4 x = *(const float4*)(Vb + (size_t)row * W_ + k0 + c4);
            *(uint4*)&Vs[row][c4] = make_uint4(tf32r(x.x), tf32r(x.y), tf32r(x.z), tf32r(x.w));
        }
        __syncthreads();
        #pragma unroll
        for (int k8 = 0; k8 < 8; k8++) {
            const int kk = k8 * 8;
            unsigned a[2][4], b[4][2];
            #pragma unroll
            for (int mf = 0; mf < 2; mf++) {
                int r = wm0 + mf*16 + g;
                a[mf][0] = Ps[r][kk + t4];
                a[mf][1] = Ps[r + 8][kk + t4];
                a[mf][2] = Ps[r][kk + t4 + 4];
                a[mf][3] = Ps[r + 8][kk + t4 + 4];
            }
            #pragma unroll
            for (int nf = 0; nf < 4; nf++) {
                int r = wn0 + nf*8 + g;
                b[nf][0] = Vs[r][kk + t4];
                b[nf][1] = Vs[r][kk + t4 + 4];
            }
            #pragma unroll
            for (int mf = 0; mf < 2; mf++)
                #pragma unroll
                for (int nf = 0; nf < 4; nf++)
                    MMA8(acc[mf][nf], a[mf], b[nf]);
        }
    }

    #pragma unroll
    for (int mf = 0; mf < 2; mf++) {
        #pragma unroll
        for (int nf = 0; nf < 4; nf++) {
            int ql = wm0 + mf*16 + g;
            int d  = wn0 + nf*8 + 2*t4;
            #pragma unroll
            for (int rr = 0; rr < 2; rr++) {
                int q = ql + rr * 8;
                float sc = srs[q];
                size_t o = ((size_t)bc * W_ + q0 + q) * F_ + h * DH_ + d;
                *(float2*)(AT + o) = make_float2(acc[mf][nf][2*rr+0] * sc,
                                                 acc[mf][nf][2*rr+1] * sc);
            }
        }
    }
}

// ---------------------------------------------------------------------------
extern "C" void kernel_launch(void* const* d_in, const int* in_sizes, int n_in,
                              void* d_out, int out_size)
{
    const float* x    = (const float*)d_in[0];
    const float* prev = (const float*)d_in[1];
    const float* mask = (const float*)d_in[2];
    const float* wq   = (const float*)d_in[3];
    const float* wqc  = (const float*)d_in[4];
    const float* bq   = (const float*)d_in[5];
    const float* wk   = (const float*)d_in[6];
    const float* wkc  = (const float*)d_in[7];
    const float* bk   = (const float*)d_in[8];
    const float* wv   = (const float*)d_in[9];
    const float* wvc  = (const float*)d_in[10];
    const float* bv   = (const float*)d_in[11];
    const float* wo   = (const float*)d_in[12];

    float* out = (float*)d_out;            // [B,C,F,W]
    float* qk  = out + (size_t)TOT_;       // [B,C,H,W,W]

    float *lin_base, *conv_base, *xt, *qt, *kt, *atT, *mx, *rs;
    cudaGetSymbolAddress((void**)&lin_base,  g_lin);
    cudaGetSymbolAddress((void**)&conv_base, g_conv);
    cudaGetSymbolAddress((void**)&xt,  g_xt);
    cudaGetSymbolAddress((void**)&qt,  g_qt);
    cudaGetSymbolAddress((void**)&kt,  g_kt);
    cudaGetSymbolAddress((void**)&atT, g_atT);
    cudaGetSymbolAddress((void**)&mx,  g_mx);
    cudaGetSymbolAddress((void**)&rs,  g_rs);

    float* lin0  = lin_base;
    float* lin1  = lin_base + (size_t)TOT_;
    float* lin2  = lin_base + (size_t)2*TOT_;
    float* cbuf0 = conv_base;
    float* cbuf1 = conv_base + (size_t)TOT_;
    float* cbuf2 = conv_base + (size_t)2*TOT_;

    rot_table_kernel<<<128, 256>>>();

    // x [bc][f][w] -> xt [bc][w][f]
    transpose_kernel<<<dim3(32, 16, BC_), dim3(32, 8)>>>(x, xt, F_);

    dim3 gg(W_/128, F_/128, BC_);   // 8, 4, 8
    gemm_tf32_kernel<<<gg, 256>>>(wq, xt, lin0);
    gemm_tf32_kernel<<<gg, 256>>>(wk, xt, lin1);
    gemm_tf32_kernel<<<gg, 256>>>(wv, xt, lin2);

    int cblocks = (TOT_/2) / 256;
    conv_rot_kernel<1><<<cblocks, 256>>>(lin0, wqc, bq, cbuf0);
    conv_rot_kernel<1><<<cblocks, 256>>>(lin1, wkc, bk, cbuf1);
    conv_rot_kernel<0><<<cblocks, 256>>>(lin2, wvc, bv, cbuf2);

    // Q,K [bch][d][w] planes -> [bch][w][d]
    transpose_kernel<<<dim3(32, 2, BCH_), dim3(32, 8)>>>(cbuf0, qt, DH_);
    transpose_kernel<<<dim3(32, 2, BCH_), dim3(32, 8)>>>(cbuf1, kt, DH_);

    cudaFuncSetAttribute(qk_mma_kernel,
                         cudaFuncAttributeMaxDynamicSharedMemorySize, QK_SMEM);
    qk_mma_kernel<<<dim3(8, 8, BCH_), 256, QK_SMEM>>>(qt, kt, prev, mask, qk);

    rowstats_kernel<<<NROWS_/8, 256>>>(qk, mx, rs);

    cudaFuncSetAttribute(av_mma_kernel,
                         cudaFuncAttributeMaxDynamicSharedMemorySize, AV_SMEM);
    av_mma_kernel<<<dim3(W_/128, BCH_), 256, AV_SMEM>>>(qk, cbuf2, mx, rs, atT);

    gemm_tf32_kernel<<<gg, 256>>>(wo, atT, out);
}